// round 2
// baseline (speedup 1.0000x reference)
#include <cuda_runtime.h>

// Problem constants
#define BN   8
#define CN   256
#define HN   64
#define WN   64
#define GN   4
#define KKN  9
#define CG   64          // channels per group
#define OCF  108         // offset-branch output channels = 3*G*K*K
#define HWN  (HN*WN)

typedef unsigned long long u64;

// packed f32x2 FMA: d = a*b + d (two independent fp32 lanes per issue)
#define FFMA2(d, a, b) asm("fma.rn.f32x2 %0, %1, %2, %0;" : "+l"(d) : "l"(a), "l"(b))
#define UNPACK2(lo, hi, v) asm("mov.b64 {%0,%1}, %2;" : "=f"(lo), "=f"(hi) : "l"(v))
#define PACK2(d, lo, hi)   asm("mov.b64 %0, {%1,%2};" : "=l"(d) : "f"(lo), "f"(hi))

// Scratch (device globals; no runtime allocation allowed)
__device__ float g_off[BN*OCF*HWN];          // offset/mask conv output
__device__ float g_out[BN*CN*HWN];           // DCN conv output (pre-LN)
__device__ float g_wT [GN*KKN*CG*CG];        // w_dcn transposed to [g][k][c][oc]

// ---------------------------------------------------------------------------
// Kernel 0: transpose w_dcn [256][64][3][3] -> g_wT[g][k][c][oc]
// ---------------------------------------------------------------------------
__global__ void __launch_bounds__(256) transpose_wdcn_k(const float* __restrict__ w_dcn)
{
    int i = blockIdx.x * 256 + threadIdx.x;
    if (i < GN*KKN*CG*CG) {
        int oc = i & 63;
        int c  = (i >> 6) & 63;
        int gk = i >> 12;          // g*9 + k
        int k  = gk % 9;
        int g  = gk / 9;
        g_wT[i] = w_dcn[((g*CG + oc)*CG + c)*KKN + k];
    }
}

// ---------------------------------------------------------------------------
// Kernel 1: offset/mask conv  (C=256 -> 108, 3x3, SAME, +bias), FFMA2 core.
// grid (HN/2, BN), block 256.  Block: 2 rows x 64 cols x 108 oc.
// Thread tile: 8 px (4 pairs) x 7 oc.
// Dynamic smem layout (floats):
//   [0            .. 16128)  ws2: [112 oc][72 ck] broadcast u64 pairs (w,w)
//   [16128        .. 18304)  xsA: [8c][4r][68]  natural patch
//   [18304        .. 20480)  xsB: [8c][4r][68]  patch shifted left by 1
// ---------------------------------------------------------------------------
#define OC_WS2F  16128
#define OC_XSA   OC_WS2F
#define OC_XSB   (OC_XSA + 8*4*68)
#define OC_SMEMF (OC_XSB + 8*4*68)

__global__ void __launch_bounds__(256) offset_conv_k(
    const float* __restrict__ x, const float* __restrict__ w_off,
    const float* __restrict__ b_off)
{
    extern __shared__ float osm[];
    float* xsA = osm + OC_XSA;
    float* xsB = osm + OC_XSB;
    const u64* W64 = (const u64*)osm;              // [112][72] u64
    const u64* A64 = (const u64*)xsA;              // rows of 34 u64
    const u64* B64 = (const u64*)xsB;

    const int h0   = blockIdx.x * 2;
    const int b    = blockIdx.y;
    const int t    = threadIdx.x;
    const int pxg  = t & 15;          // 16 pixel groups of 8
    const int ocg  = t >> 4;          // 16 oc groups of 7
    const int px0  = pxg * 8;
    const int prow = px0 >> 6;        // 0 or 1
    const int pcol0 = px0 & 63;
    const int pc2  = pcol0 >> 1;      // u64 column base (0..28)

    u64 acc2[7][4];
#pragma unroll
    for (int j = 0; j < 7; j++)
#pragma unroll
        for (int i = 0; i < 4; i++) acc2[j][i] = 0ull;

    for (int cb = 0; cb < CN; cb += 8) {
        __syncthreads();
        // Load x patch: 8 ch x 4 rows x 66 cols into A (natural) and B (shift-1)
        for (int i = t; i < 8*4*66; i += 256) {
            int c   = i / 264;
            int rem = i - c*264;
            int r   = rem / 66;
            int col = rem - r*66;
            int y   = h0 - 1 + r;
            int xx  = col - 1;
            float v = 0.f;
            if (y >= 0 && y < HN && xx >= 0 && xx < WN)
                v = x[((b*CN + cb + c)*HN + y)*WN + xx];
            int rbase = (c*4 + r)*68;
            xsA[rbase + col] = v;
            if (col > 0) xsB[rbase + col - 1] = v;
        }
        // Load weight panel broadcast-duplicated: ws2[oc][ck] = (w,w)
        for (int i = t; i < 112*72; i += 256) {
            int oc  = i / 72;
            int rem = i - oc*72;
            float w = 0.f;
            if (oc < OCF) {
                int c = rem / 9;
                int k = rem - c*9;
                w = w_off[(oc*CN + cb + c)*KKN + k];
            }
            u64 p; PACK2(p, w, w);
            ((u64*)osm)[i] = p;
        }
        __syncthreads();

#pragma unroll
        for (int c8 = 0; c8 < 8; c8++) {
#pragma unroll
            for (int ky = 0; ky < 3; ky++) {
                const u64* rA = A64 + (c8*4 + prow + ky)*34 + pc2;
                const u64* rB = B64 + (c8*4 + prow + ky)*34 + pc2;
                u64 a0 = rA[0], a1 = rA[1], a2 = rA[2], a3 = rA[3], a4 = rA[4];
                u64 b0 = rB[0], b1 = rB[1], b2 = rB[2], b3 = rB[3];
                const u64* wrow = W64 + ocg*7*72 + c8*9 + ky*3;
#pragma unroll
                for (int j = 0; j < 7; j++) {
                    const u64* wj = wrow + j*72;
                    u64 w0 = wj[0], w1 = wj[1], w2 = wj[2];
                    FFMA2(acc2[j][0], w0, a0);
                    FFMA2(acc2[j][1], w0, a1);
                    FFMA2(acc2[j][2], w0, a2);
                    FFMA2(acc2[j][3], w0, a3);
                    FFMA2(acc2[j][0], w1, b0);
                    FFMA2(acc2[j][1], w1, b1);
                    FFMA2(acc2[j][2], w1, b2);
                    FFMA2(acc2[j][3], w1, b3);
                    FFMA2(acc2[j][0], w2, a1);
                    FFMA2(acc2[j][1], w2, a2);
                    FFMA2(acc2[j][2], w2, a3);
                    FFMA2(acc2[j][3], w2, a4);
                }
            }
        }
    }

    const int h = h0 + prow;
#pragma unroll
    for (int j = 0; j < 7; j++) {
        int oc = ocg*7 + j;
        if (oc < OCF) {
            float bo = b_off[oc];
            float* op = g_off + ((b*OCF + oc)*HN + h)*WN + pcol0;
#pragma unroll
            for (int i = 0; i < 4; i++) {
                float lo, hi;
                UNPACK2(lo, hi, acc2[j][i]);
                float2 v = make_float2(lo + bo, hi + bo);
                *reinterpret_cast<float2*>(op + 2*i) = v;
            }
        }
    }
}

// ---------------------------------------------------------------------------
// Kernel 2: deformable sampling + grouped conv, FFMA2 GEMM core.
// grid (HN/2, GN, BN), block 256, dynamic smem.
// Dynamic smem layout (floats):
//   [0     ..  8192)  Wsm2: [64c][64 oc-pairs] broadcast u64 (w,w)
//   [8192  .. 16640)  S:    [64c][SPITCH=132]
//   [16640 .. 17152)  wwt:  [4][128]
//   [17152 .. 17664)  widx: [4][128] (int)
// ---------------------------------------------------------------------------
#define SPITCH     132
#define SM2_S      8192
#define SM2_WWT    (SM2_S + CG*SPITCH)
#define SM2_WIDX   (SM2_WWT + 4*128)
#define SM2_FLOATS (SM2_WIDX + 4*128)

__global__ void __launch_bounds__(256) dcn_k(
    const float* __restrict__ x, const float* __restrict__ b_dcn)
{
    extern __shared__ float sm[];
    float* Wsm2 = sm;
    float* S    = sm + SM2_S;
    float* wwt  = sm + SM2_WWT;
    int*   widx = (int*)(sm + SM2_WIDX);
    const u64* W64 = (const u64*)Wsm2;    // [64c][64] u64
    const u64* S64 = (const u64*)S;       // rows of 66 u64

    const int h0 = blockIdx.x * 2;
    const int g  = blockIdx.y;
    const int b  = blockIdx.z;
    const int t  = threadIdx.x;
    const int px0 = (t & 15) * 8;      // 16 px groups of 8
    const int oc0 = (t >> 4) * 4;      // 16 oc groups of 4
    const int px2 = px0 >> 1;          // u64 column

    u64 acc2[4][4];
#pragma unroll
    for (int j = 0; j < 4; j++)
#pragma unroll
        for (int i = 0; i < 4; i++) acc2[j][i] = 0ull;

    const int pB     = t & 127;        // pixel for Phase B
    const int cstart = t >> 7;         // 0 or 1
    const float* xb  = x + (b*CN + g*CG)*HWN;

    for (int k = 0; k < KKN; k++) {
        // ---- Phase A: per-pixel bilinear corner data (threads 0..127) ----
        if (t < 128) {
            int p  = t;
            int h  = h0 + (p >> 6);
            int w  = p & 63;
            int ky = k / 3 - 1;
            int kx = k - (k/3)*3 - 1;
            int sp = h*WN + w;
            float oy = g_off[b*OCF*HWN + ((g*KKN + k)*2    )*HWN + sp];
            float ox = g_off[b*OCF*HWN + ((g*KKN + k)*2 + 1)*HWN + sp];
            float mz = g_off[b*OCF*HWN + (2*GN*KKN + g*KKN + k)*HWN + sp];
            float mk = 1.f / (1.f + expf(-mz));
            float py  = (float)(h + ky) + oy;
            float pxx = (float)(w + kx) + ox;
            float y0f = floorf(py),  x0f = floorf(pxx);
            float wy1 = py - y0f,    wx1 = pxx - x0f;
            float wy0 = 1.f - wy1,   wx0 = 1.f - wx1;
            int y0 = (int)y0f, x0i = (int)x0f;
            int y1 = y0 + 1,   x1i = x0i + 1;
            bool vy0 = (y0 >= 0) & (y0 < HN);
            bool vy1 = (y1 >= 0) & (y1 < HN);
            bool vx0 = (x0i >= 0) & (x0i < WN);
            bool vx1 = (x1i >= 0) & (x1i < WN);
            int y0c = min(max(y0, 0), HN-1), y1c = min(max(y1, 0), HN-1);
            int x0c = min(max(x0i,0), WN-1), x1c = min(max(x1i,0), WN-1);
            widx[0*128+p] = y0c*WN + x0c;
            widx[1*128+p] = y0c*WN + x1c;
            widx[2*128+p] = y1c*WN + x0c;
            widx[3*128+p] = y1c*WN + x1c;
            wwt [0*128+p] = (vy0 && vx0) ? wy0*wx0*mk : 0.f;
            wwt [1*128+p] = (vy0 && vx1) ? wy0*wx1*mk : 0.f;
            wwt [2*128+p] = (vy1 && vx0) ? wy1*wx0*mk : 0.f;
            wwt [3*128+p] = (vy1 && vx1) ? wy1*wx1*mk : 0.f;
        }
        // ---- Phase A2: stage weight panel broadcast-duplicated ----
        {
            const float* wt = g_wT + (g*KKN + k)*CG*CG;
            u64* wdst = (u64*)Wsm2;
            for (int i = t; i < CG*CG; i += 256) {
                float w = wt[i];
                u64 p; PACK2(p, w, w);
                wdst[i] = p;     // i = c*64 + oc
            }
        }
        __syncthreads();

        // ---- Phase B: gather sampled values S[c][p] ----
        {
            float w0 = wwt[0*128+pB], w1 = wwt[1*128+pB];
            float w2 = wwt[2*128+pB], w3 = wwt[3*128+pB];
            int   i0 = widx[0*128+pB], i1 = widx[1*128+pB];
            int   i2 = widx[2*128+pB], i3 = widx[3*128+pB];
#pragma unroll 4
            for (int c = cstart; c < CG; c += 2) {
                const float* xp = xb + c*HWN;
                S[c*SPITCH + pB] = w0*xp[i0] + w1*xp[i1] + w2*xp[i2] + w3*xp[i3];
            }
        }
        __syncthreads();

        // ---- Phase C: FFMA2 GEMM  acc[oc][px] += W[c][oc] * S[c][px] ----
#pragma unroll 8
        for (int c = 0; c < CG; c++) {
            const u64* wp = W64 + c*64 + oc0;
            const u64* sp = S64 + c*66 + px2;
            u64 w0 = wp[0], w1 = wp[1], w2 = wp[2], w3 = wp[3];
            u64 s0 = sp[0], s1 = sp[1], s2 = sp[2], s3 = sp[3];
            FFMA2(acc2[0][0], w0, s0); FFMA2(acc2[0][1], w0, s1);
            FFMA2(acc2[0][2], w0, s2); FFMA2(acc2[0][3], w0, s3);
            FFMA2(acc2[1][0], w1, s0); FFMA2(acc2[1][1], w1, s1);
            FFMA2(acc2[1][2], w1, s2); FFMA2(acc2[1][3], w1, s3);
            FFMA2(acc2[2][0], w2, s0); FFMA2(acc2[2][1], w2, s1);
            FFMA2(acc2[2][2], w2, s2); FFMA2(acc2[2][3], w2, s3);
            FFMA2(acc2[3][0], w3, s0); FFMA2(acc2[3][1], w3, s1);
            FFMA2(acc2[3][2], w3, s2); FFMA2(acc2[3][3], w3, s3);
        }
        __syncthreads();
    }

    // ---- epilogue: +bias, store ----
    const int h   = h0 + (px0 >> 6);
    const int w0c = px0 & 63;
#pragma unroll
    for (int j = 0; j < 4; j++) {
        int ocgl = g*CG + oc0 + j;
        float bd = b_dcn[ocgl];
        float* op = g_out + ((b*CN + ocgl)*HN + h)*WN + w0c;
#pragma unroll
        for (int i = 0; i < 4; i++) {
            float lo, hi;
            UNPACK2(lo, hi, acc2[j][i]);
            *reinterpret_cast<float2*>(op + 2*i) = make_float2(lo + bd, hi + bd);
        }
    }
}

// ---------------------------------------------------------------------------
// Kernel 3: LayerNorm over C + sigmoid + gate, full 64-px row per block.
// grid (HN, BN), block 256, dynamic smem 64KB tile [256][64].
// ---------------------------------------------------------------------------
__global__ void __launch_bounds__(256) ln_gate_k(
    const float* __restrict__ x, const float* __restrict__ gamma,
    const float* __restrict__ beta, float* __restrict__ out)
{
    extern __shared__ float tile[];   // [256][64]
    __shared__ float rs[4][64];
    __shared__ float rq[4][64];
    __shared__ float smu[64], srinv[64];
    __shared__ float sg[CN], sb[CN];

    const int b    = blockIdx.y;
    const int h    = blockIdx.x;
    const int t    = threadIdx.x;
    const int base = b*CN*HWN + h*WN;

    if (t < CN) { sg[t] = gamma[t]; sb[t] = beta[t]; }

    // load tile: 16 float4 per thread
    for (int i = t*4; i < CN*64; i += 1024) {
        int c = i >> 6, p = i & 63;
        *reinterpret_cast<float4*>(&tile[c*64 + p]) =
            *reinterpret_cast<const float4*>(g_out + base + c*HWN + p);
    }
    __syncthreads();
    {
        int p = t & 63, part = t >> 6;
        float s = 0.f, q = 0.f;
#pragma unroll 8
        for (int c = part; c < CN; c += 4) {
            float v = tile[c*64 + p];
            s += v; q += v*v;
        }
        rs[part][p] = s; rq[part][p] = q;
    }
    __syncthreads();
    if (t < 64) {
        float s = 0.f, q = 0.f;
#pragma unroll
        for (int part = 0; part < 4; part++) { s += rs[part][t]; q += rq[part][t]; }
        float mu  = s * (1.f/CN);
        float var = fmaxf(q * (1.f/CN) - mu*mu, 0.f);
        smu[t]   = mu;
        srinv[t] = rsqrtf(var + 1e-5f);
    }
    __syncthreads();
    for (int i = t*4; i < CN*64; i += 1024) {
        int c = i >> 6, p = i & 63;
        float4 v = *reinterpret_cast<const float4*>(&tile[c*64 + p]);
        float4 xv = *reinterpret_cast<const float4*>(x + base + c*HWN + p);
        float gm = sg[c], bt = sb[c];
        float4 o;
        {
            float z = (v.x - smu[p  ]) * srinv[p  ] * gm + bt;
            o.x = xv.x / (1.f + expf(-z));
            z = (v.y - smu[p+1]) * srinv[p+1] * gm + bt;
            o.y = xv.y / (1.f + expf(-z));
            z = (v.z - smu[p+2]) * srinv[p+2] * gm + bt;
            o.z = xv.z / (1.f + expf(-z));
            z = (v.w - smu[p+3]) * srinv[p+3] * gm + bt;
            o.w = xv.w / (1.f + expf(-z));
        }
        *reinterpret_cast<float4*>(out + base + c*HWN + p) = o;
    }
}

// ---------------------------------------------------------------------------
// Entry point
// ---------------------------------------------------------------------------
extern "C" void kernel_launch(void* const* d_in, const int* in_sizes, int n_in,
                              void* d_out, int out_size)
{
    const float* x     = (const float*)d_in[0];
    const float* w_off = (const float*)d_in[1];
    const float* b_off = (const float*)d_in[2];
    const float* w_dcn = (const float*)d_in[3];
    const float* b_dcn = (const float*)d_in[4];
    const float* gamma = (const float*)d_in[5];
    const float* beta  = (const float*)d_in[6];
    float* out = (float*)d_out;

    (void)in_sizes; (void)n_in; (void)out_size;

    static int attr_done = 0;
    cudaFuncSetAttribute(offset_conv_k, cudaFuncAttributeMaxDynamicSharedMemorySize,
                         OC_SMEMF * (int)sizeof(float));
    cudaFuncSetAttribute(dcn_k, cudaFuncAttributeMaxDynamicSharedMemorySize,
                         SM2_FLOATS * (int)sizeof(float));
    cudaFuncSetAttribute(ln_gate_k, cudaFuncAttributeMaxDynamicSharedMemorySize,
                         CN * 64 * (int)sizeof(float));
    (void)attr_done;

    transpose_wdcn_k<<<(GN*KKN*CG*CG + 255)/256, 256>>>(w_dcn);
    offset_conv_k<<<dim3(HN/2, BN), 256, OC_SMEMF * sizeof(float)>>>(x, w_off, b_off);
    dcn_k<<<dim3(HN/2, GN, BN), 256, SM2_FLOATS * sizeof(float)>>>(x, b_dcn);
    ln_gate_k<<<dim3(HN, BN), 256, CN * 64 * sizeof(float)>>>(x, gamma, beta, out);
}

// round 4
// speedup vs baseline: 2.4980x; 2.4980x over previous
#include <cuda_runtime.h>
#include <cstdint>

// Problem constants
#define BN   8
#define CN   256
#define HN   64
#define WN   64
#define GN   4
#define KKN  9
#define CG   64
#define OCF  108
#define OCP  128      // padded offset-conv out channels
#define HWN  (HN*WN)

// ---------------------------------------------------------------------------
// Scratch
// ---------------------------------------------------------------------------
__device__ float g_off[BN*OCF*HWN];          // offset/mask conv output
__device__ float g_out[BN*CN*HWN];           // DCN conv output (pre-LN)
__device__ float g_wT [GN*KKN*CG*CG];        // w_dcn as [g][k][oc][c], tf32-rounded
__device__ float g_wA [8*KKN*OCP*32];        // w_off as [cc][kk][oc 128][c 32], tf32-rounded

// ---------------------------------------------------------------------------
// helpers
// ---------------------------------------------------------------------------
__device__ __forceinline__ float tf32r(float v) {
    uint32_t u; asm("cvt.rna.tf32.f32 %0, %1;" : "=r"(u) : "f"(v));
    return __uint_as_float(u);
}
// m16n8k8 tf32 mma, D += A*B. a: 4 regs, b: 2 regs, d: 4 fp32.
__device__ __forceinline__ void mma_tf32(float* d, const uint32_t* a,
                                         uint32_t b0, uint32_t b1) {
    asm volatile(
        "mma.sync.aligned.m16n8k8.row.col.f32.tf32.tf32.f32 "
        "{%0,%1,%2,%3}, {%4,%5,%6,%7}, {%8,%9}, {%0,%1,%2,%3};"
        : "+f"(d[0]), "+f"(d[1]), "+f"(d[2]), "+f"(d[3])
        : "r"(a[0]), "r"(a[1]), "r"(a[2]), "r"(a[3]), "r"(b0), "r"(b1));
}

// ---------------------------------------------------------------------------
// Kernel 0a: w_dcn [256][64][3][3] -> g_wT[g][k][oc][c] (tf32-rounded)
// ---------------------------------------------------------------------------
__global__ void __launch_bounds__(256) transpose_wdcn_k(const float* __restrict__ w_dcn)
{
    int i = blockIdx.x * 256 + threadIdx.x;
    if (i < GN*KKN*CG*CG) {
        int c  = i & 63;
        int oc = (i >> 6) & 63;
        int gk = i >> 12;              // g*9 + k
        int k  = gk % 9;
        int g  = gk / 9;
        g_wT[i] = tf32r(w_dcn[((g*CG + oc)*CG + c)*KKN + k]);
    }
}

// ---------------------------------------------------------------------------
// Kernel 0b: w_off -> g_wA[cc][kk][oc(128 pad)][c 32] (tf32-rounded)
// ---------------------------------------------------------------------------
__global__ void __launch_bounds__(256) prep_wA_k(const float* __restrict__ w_off)
{
    int i = blockIdx.x * 256 + threadIdx.x;
    if (i >= 8*KKN*OCP*32) return;
    int tile = i >> 12;                // cc*9 + kk  (128*32 = 4096)
    int r    = i & 4095;
    int oc   = r >> 5;
    int c    = r & 31;
    int kk   = tile % 9;
    int cc   = tile / 9;
    float w = 0.f;
    if (oc < OCF) w = tf32r(w_off[(oc*CN + cc*32 + c)*KKN + kk]);
    g_wA[i] = w;
}

// ---------------------------------------------------------------------------
// Kernel 1: offset/mask conv via mma.sync tf32.
// grid (HN/2, BN), block 256 (8 warps). Block: 2 rows x 64 px x 128 oc(pad).
// Warp: 2 m-tiles(32 oc) x 8 n-tiles(64 px, one h row).
// smem (floats): patch [32c][4r][66] @0 (8448); Wt [128oc][36] @8448 (4608)
// Pitches chosen for conflict-free fragment LDS:
//   patch c-stride 264 (mod32=8), Wt pitch 36 (mod32=4).
// ---------------------------------------------------------------------------
#define OFC_WT     8448
#define OFC_FLOATS (OFC_WT + OCP*36)

__global__ void __launch_bounds__(256, 2) offset_conv_mma_k(
    const float* __restrict__ x, const float* __restrict__ b_off)
{
    extern __shared__ float sm[];
    float* patch = sm;
    float* Wt    = sm + OFC_WT;
    const uint32_t* PU  = (const uint32_t*)patch;
    const uint32_t* WtU = (const uint32_t*)Wt;

    const int h0  = blockIdx.x * 2;
    const int b   = blockIdx.y;
    const int t   = threadIdx.x;
    const int wid = t >> 5;
    const int lane = t & 31;
    const int lm4 = lane & 3;
    const int ld4 = lane >> 2;
    const int mg  = wid & 3;          // m-group: oc base mg*32
    const int ng  = wid >> 2;         // n-group: px row (0/1)

    float D[2][8][4];
#pragma unroll
    for (int s = 0; s < 2; s++)
#pragma unroll
        for (int n = 0; n < 8; n++)
#pragma unroll
            for (int i = 0; i < 4; i++) D[s][n][i] = 0.f;

    for (int cc = 0; cc < 8; cc++) {
        __syncthreads();      // prior mma reads of patch done
        // load patch: 32 ch x 4 rows (h0-1..h0+2) x 66 cols, tf32-rounded
        for (int i = t; i < 32*4*66; i += 256) {
            int c   = i / 264;
            int rem = i - c*264;
            int r   = rem / 66;
            int col = rem - r*66;
            int y   = h0 - 1 + r;
            int xx  = col - 1;
            float v = 0.f;
            if (y >= 0 && y < HN && xx >= 0 && xx < WN)
                v = x[((b*CN + cc*32 + c)*HN + y)*WN + xx];
            patch[c*264 + r*66 + col] = tf32r(v);
        }
        for (int kk = 0; kk < KKN; kk++) {
            __syncthreads();  // Wt readers done (and patch visible on kk=0)
            // stage Wt tile [128][32] -> [128][36]
            {
                const float4* src = (const float4*)(g_wA + (cc*9 + kk)*4096);
                for (int i = t; i < 1024; i += 256) {
                    float4 v = src[i];
                    int oc = i >> 3, c4 = (i & 7) * 4;
                    *reinterpret_cast<float4*>(&Wt[oc*36 + c4]) = v;
                }
            }
            __syncthreads();

            const int ky = kk / 3, kx = kk - (kk/3)*3;
            const int rbase = (ng + ky)*66 + kx + ld4;
#pragma unroll
            for (int step = 0; step < 4; step++) {
                const int k0 = step*8;
                uint32_t a[2][4];
#pragma unroll
                for (int s = 0; s < 2; s++) {
                    int ro = (mg*32 + s*16 + ld4)*36 + k0 + lm4;
                    a[s][0] = WtU[ro];
                    a[s][1] = WtU[ro + 8*36];
                    a[s][2] = WtU[ro + 4];
                    a[s][3] = WtU[ro + 8*36 + 4];
                }
                const int bb = (k0 + lm4)*264 + rbase;
#pragma unroll
                for (int nt = 0; nt < 8; nt++) {
                    uint32_t b0 = PU[bb + nt*8];
                    uint32_t b1 = PU[bb + nt*8 + 4*264];
                    mma_tf32(D[0][nt], a[0], b0, b1);
                    mma_tf32(D[1][nt], a[1], b0, b1);
                }
            }
        }
    }

    // epilogue: +bias, store (oc < 108 only)
    const int h = h0 + ng;
#pragma unroll
    for (int s = 0; s < 2; s++) {
#pragma unroll
        for (int nt = 0; nt < 8; nt++) {
            int ocA = mg*32 + s*16 + ld4;
            int ocB = ocA + 8;
            int w   = nt*8 + lm4*2;
            if (ocA < OCF) {
                float bo = b_off[ocA];
                *reinterpret_cast<float2*>(&g_off[((b*OCF + ocA)*HN + h)*WN + w])
                    = make_float2(D[s][nt][0] + bo, D[s][nt][1] + bo);
            }
            if (ocB < OCF) {
                float bo = b_off[ocB];
                *reinterpret_cast<float2*>(&g_off[((b*OCF + ocB)*HN + h)*WN + w])
                    = make_float2(D[s][nt][2] + bo, D[s][nt][3] + bo);
            }
        }
    }
}

// ---------------------------------------------------------------------------
// Kernel 2: deformable sampling + grouped conv via mma.sync tf32.
// grid (HN/4, GN, BN), block 256 (8 warps). Block: 4 rows x 64 px x 64 oc.
// Warp: 2 m-tiles(32 oc) x 8 n-tiles(64 px, one h row).
// smem (floats): Wsm [64oc][68] @0 (4352); S [64c][264] @4352 (16896)
// ---------------------------------------------------------------------------
#define DCN_S      4352
#define DCN_FLOATS (DCN_S + CG*264)

__global__ void __launch_bounds__(256, 2) dcn_mma_k(
    const float* __restrict__ x, const float* __restrict__ b_dcn)
{
    extern __shared__ float sm[];
    float* Wsm = sm;
    float* S   = sm + DCN_S;
    const uint32_t* WU = (const uint32_t*)Wsm;
    const uint32_t* SU = (const uint32_t*)S;

    const int h0 = blockIdx.x * 4;
    const int g  = blockIdx.y;
    const int b  = blockIdx.z;
    const int t  = threadIdx.x;
    const int wid = t >> 5;
    const int lane = t & 31;
    const int lm4 = lane & 3;
    const int ld4 = lane >> 2;
    const int mg  = wid & 1;          // oc base mg*32
    const int ng  = wid >> 1;         // px row (0..3)

    const int pxA = t;                // pixel owned by this thread (phase A + gather)
    const int hA  = h0 + (t >> 6);
    const int wA  = t & 63;
    const float* xb = x + (b*CN + g*CG)*HWN;

    float D[2][8][4];
#pragma unroll
    for (int s = 0; s < 2; s++)
#pragma unroll
        for (int n = 0; n < 8; n++)
#pragma unroll
            for (int i = 0; i < 4; i++) D[s][n][i] = 0.f;

    for (int k = 0; k < KKN; k++) {
        __syncthreads();   // previous mma done reading S/Wsm
        // ---- bilinear corner data (registers, this thread's pixel) ----
        int i0, i1, i2, i3; float w0, w1, w2, w3;
        {
            int ky = k / 3 - 1;
            int kx = k - (k/3)*3 - 1;
            int sp = hA*WN + wA;
            const float* ob = g_off + b*OCF*HWN;
            float oy = ob[((g*KKN + k)*2    )*HWN + sp];
            float ox = ob[((g*KKN + k)*2 + 1)*HWN + sp];
            float mz = ob[(2*GN*KKN + g*KKN + k)*HWN + sp];
            float mk = 1.f / (1.f + expf(-mz));
            float py  = (float)(hA + ky) + oy;
            float pxx = (float)(wA + kx) + ox;
            float y0f = floorf(py),  x0f = floorf(pxx);
            float wy1 = py - y0f,    wx1 = pxx - x0f;
            float wy0 = 1.f - wy1,   wx0 = 1.f - wx1;
            int y0 = (int)y0f, x0i = (int)x0f;
            int y1 = y0 + 1,   x1i = x0i + 1;
            bool vy0 = (y0 >= 0) & (y0 < HN);
            bool vy1 = (y1 >= 0) & (y1 < HN);
            bool vx0 = (x0i >= 0) & (x0i < WN);
            bool vx1 = (x1i >= 0) & (x1i < WN);
            int y0c = min(max(y0, 0), HN-1), y1c = min(max(y1, 0), HN-1);
            int x0c = min(max(x0i,0), WN-1), x1c = min(max(x1i,0), WN-1);
            i0 = y0c*WN + x0c;  i1 = y0c*WN + x1c;
            i2 = y1c*WN + x0c;  i3 = y1c*WN + x1c;
            w0 = (vy0 && vx0) ? wy0*wx0*mk : 0.f;
            w1 = (vy0 && vx1) ? wy0*wx1*mk : 0.f;
            w2 = (vy1 && vx0) ? wy1*wx0*mk : 0.f;
            w3 = (vy1 && vx1) ? wy1*wx1*mk : 0.f;
        }
        // ---- stage weight tile [64 oc][64 c] -> Wsm[oc*68 + c] ----
        {
            const float* wt = g_wT + (g*KKN + k)*CG*CG;
            for (int i = t; i < CG*CG; i += 256)
                Wsm[(i >> 6)*68 + (i & 63)] = wt[i];
        }
        // ---- gather: S[c][pxA] for all 64 channels ----
#pragma unroll 4
        for (int c = 0; c < CG; c++) {
            const float* xp = xb + c*HWN;
            float v = w0*xp[i0] + w1*xp[i1] + w2*xp[i2] + w3*xp[i3];
            S[c*264 + pxA] = tf32r(v);
        }
        __syncthreads();

        // ---- mma: K=64 -> 8 k8-steps ----
#pragma unroll
        for (int step = 0; step < 8; step++) {
            const int k0 = step*8;
            uint32_t a[2][4];
#pragma unroll
            for (int s = 0; s < 2; s++) {
                int ro = (mg*32 + s*16 + ld4)*68 + k0 + lm4;
                a[s][0] = WU[ro];
                a[s][1] = WU[ro + 8*68];
                a[s][2] = WU[ro + 4];
                a[s][3] = WU[ro + 8*68 + 4];
            }
            const int bb = (k0 + lm4)*264 + ng*64 + ld4;
#pragma unroll
            for (int nt = 0; nt < 8; nt++) {
                uint32_t b0 = SU[bb + nt*8];
                uint32_t b1 = SU[bb + nt*8 + 4*264];
                mma_tf32(D[0][nt], a[0], b0, b1);
                mma_tf32(D[1][nt], a[1], b0, b1);
            }
        }
    }

    // ---- epilogue: +bias, store ----
    const int h = h0 + ng;
#pragma unroll
    for (int s = 0; s < 2; s++) {
#pragma unroll
        for (int nt = 0; nt < 8; nt++) {
            int ocA = g*CG + mg*32 + s*16 + ld4;
            int ocB = ocA + 8;
            int w   = nt*8 + lm4*2;
            float boA = b_dcn[ocA], boB = b_dcn[ocB];
            *reinterpret_cast<float2*>(&g_out[((b*CN + ocA)*HN + h)*WN + w])
                = make_float2(D[s][nt][0] + boA, D[s][nt][1] + boA);
            *reinterpret_cast<float2*>(&g_out[((b*CN + ocB)*HN + h)*WN + w])
                = make_float2(D[s][nt][2] + boB, D[s][nt][3] + boB);
        }
    }
}

// ---------------------------------------------------------------------------
// Kernel 3: LayerNorm over C + sigmoid + gate (proven round-1 version)
// ---------------------------------------------------------------------------
__global__ void __launch_bounds__(256) ln_gate_k(
    const float* __restrict__ x, const float* __restrict__ gamma,
    const float* __restrict__ beta, float* __restrict__ out)
{
    __shared__ float tile[CN][32];
    __shared__ float rs[8][32];
    __shared__ float rq[8][32];
    __shared__ float smu[32], srinv[32];

    const int b    = blockIdx.y;
    const int h    = blockIdx.x >> 1;
    const int wseg = (blockIdx.x & 1) * 32;
    const int t    = threadIdx.x;
    const int base = b*CN*HWN + h*WN + wseg;

    for (int i = t; i < CN*32; i += 256) {
        int c = i >> 5, p = i & 31;
        tile[c][p] = g_out[base + c*HWN + p];
    }
    __syncthreads();
    {
        int p = t & 31, part = t >> 5;
        float s = 0.f, q = 0.f;
        for (int c = part; c < CN; c += 8) {
            float v = tile[c][p];
            s += v; q += v*v;
        }
        rs[part][p] = s; rq[part][p] = q;
    }
    __syncthreads();
    if (t < 32) {
        float s = 0.f, q = 0.f;
#pragma unroll
        for (int part = 0; part < 8; part++) { s += rs[part][t]; q += rq[part][t]; }
        float mu  = s * (1.f/CN);
        float var = fmaxf(q * (1.f/CN) - mu*mu, 0.f);
        smu[t]   = mu;
        srinv[t] = rsqrtf(var + 1e-5f);
    }
    __syncthreads();
    for (int i = t; i < CN*32; i += 256) {
        int c = i >> 5, p = i & 31;
        float z = (tile[c][p] - smu[p]) * srinv[p] * gamma[c] + beta[c];
        float a = 1.f / (1.f + expf(-z));
        int idx = base + c*HWN + p;
        out[idx] = x[idx] * a;
    }
}

// ---------------------------------------------------------------------------
// Entry point
// ---------------------------------------------------------------------------
extern "C" void kernel_launch(void* const* d_in, const int* in_sizes, int n_in,
                              void* d_out, int out_size)
{
    const float* x     = (const float*)d_in[0];
    const float* w_off = (const float*)d_in[1];
    const float* b_off = (const float*)d_in[2];
    const float* w_dcn = (const float*)d_in[3];
    const float* b_dcn = (const float*)d_in[4];
    const float* gamma = (const float*)d_in[5];
    const float* beta  = (const float*)d_in[6];
    float* out = (float*)d_out;

    (void)in_sizes; (void)n_in; (void)out_size;

    cudaFuncSetAttribute(offset_conv_mma_k, cudaFuncAttributeMaxDynamicSharedMemorySize,
                         OFC_FLOATS * (int)sizeof(float));
    cudaFuncSetAttribute(dcn_mma_k, cudaFuncAttributeMaxDynamicSharedMemorySize,
                         DCN_FLOATS * (int)sizeof(float));

    transpose_wdcn_k<<<(GN*KKN*CG*CG + 255)/256, 256>>>(w_dcn);
    prep_wA_k<<<(8*KKN*OCP*32 + 255)/256, 256>>>(w_off);
    offset_conv_mma_k<<<dim3(HN/2, BN), 256, OFC_FLOATS * sizeof(float)>>>(x, b_off);
    dcn_mma_k<<<dim3(HN/4, GN, BN), 256, DCN_FLOATS * sizeof(float)>>>(x, b_dcn);
    ln_gate_k<<<dim3(HN*2, BN), 256>>>(x, gamma, beta, out);
}